// round 15
// baseline (speedup 1.0000x reference)
#include <cuda_runtime.h>
#include <cuda_fp16.h>
#include <stdint.h>

// ============================================================================
// FibonacciKAN via monomial re-expansion, legacy mma.sync path.
//   Y[32768,256] = A[32768,1024] @ W[1024,256] + bias, A = powers of tanh(x)
// R13: persistent W-resident CTAs. Grid = 148 (4 col-slices x 37). Each CTA
// loads its 64-col W slice into SMEM ONCE (129KB), then loops over ~7 row
// tiles of 128 rows. Steady state has no cp.async/cp_wait -- the two taxes
// R12 left (per-kt W restage gate + 2.3-wave quantization) are removed.
// Warp tile 64x32 with k-split pairs (kk 0-1 / 2-3) + smem reduction.
// ============================================================================

#define B_ROWS 32768
#define IN_DIM 256
#define OUT_DIM 256
#define KDIM 1024
#define BM 128                // rows per tile
#define BN 64                 // cols per CTA (col slice)
#define NCOLS 4
#define NRCTA 37
#define NTILES (B_ROWS / BM)  // 256
#define BK 64
#define NKT (KDIM / BK)       // 16
#define NTHREADS 256

#define SA 72                 // A row stride in halves (144B) -> conflict-free
#define ABYTES (BM * SA * 2)  // 18432
#define WSTRIDE 2064          // W bytes per col row (2048 + 16 pad) -> conflict-free
#define SM_A0 0
#define SM_A1 ABYTES
#define SM_W  (2 * ABYTES)                  // 36864
#define SM_RED (SM_W + BN * WSTRIDE)        // 36864 + 132096 = 168960
#define SM_TOTAL (SM_RED + 32768)           // 201728 bytes, 1 CTA/SM

__device__ __half g_W[OUT_DIM * KDIM];   // [o][k], k-contiguous
__device__ float  g_bias[OUT_DIM];

// ---------------------------------------------------------------------------
__device__ __forceinline__ uint32_t smem_u32(const void* p) {
    uint32_t a;
    asm("{ .reg .u64 t; cvta.to.shared.u64 t, %1; cvt.u32.u64 %0, t; }"
        : "=r"(a) : "l"(p));
    return a;
}
__device__ __forceinline__ void cp_async16(uint32_t dst, const void* src) {
    asm volatile("cp.async.cg.shared.global [%0], [%1], 16;"
                 :: "r"(dst), "l"(src) : "memory");
}
__device__ __forceinline__ void cp_commit() {
    asm volatile("cp.async.commit_group;" ::: "memory");
}
__device__ __forceinline__ void cp_wait0() {
    asm volatile("cp.async.wait_group 0;" ::: "memory");
}
__device__ __forceinline__ void ldsm_x4(uint32_t& r0, uint32_t& r1,
                                        uint32_t& r2, uint32_t& r3, uint32_t addr) {
    asm volatile("ldmatrix.sync.aligned.m8n8.x4.shared.b16 {%0,%1,%2,%3}, [%4];"
                 : "=r"(r0), "=r"(r1), "=r"(r2), "=r"(r3) : "r"(addr));
}
__device__ __forceinline__ uint32_t pack_h2(float a, float b) {
    __half2 h = __floats2half2_rn(a, b);
    return *(uint32_t*)&h;
}
__device__ __forceinline__ float tanh_fast(float x) {
    float y;
    asm("tanh.approx.f32 %0, %1;" : "=f"(y) : "f"(x));
    return y;
}

// ---------------------------------------------------------------------------
// Weight prep: C[i][o][d] -> monomial W[o][k=i*4+p] fp16 + bias[o]
// ---------------------------------------------------------------------------
__global__ void prep_weights_kernel(const float* __restrict__ C) {
    int o = blockIdx.x;
    int i = threadIdx.x;
    const float* c = C + ((size_t)i * OUT_DIM + o) * 6;
    float c1 = c[1], c2 = c[2], c3 = c[3], c4 = c[4], c5 = c[5];
    __half2* dst = (__half2*)(g_W + (size_t)o * KDIM + i * 4);
    dst[0] = __floats2half2_rn(c2 + 2.0f * c4, c3 + 3.0f * c5);
    dst[1] = __floats2half2_rn(c4, c5);

    float v = c1 + c3 + c5;
    #pragma unroll
    for (int s = 16; s > 0; s >>= 1)
        v += __shfl_xor_sync(0xFFFFFFFF, v, s);
    __shared__ float sb[8];
    if ((i & 31) == 0) sb[i >> 5] = v;
    __syncthreads();
    if (i < 8) {
        float w = sb[i];
        #pragma unroll
        for (int s = 4; s > 0; s >>= 1)
            w += __shfl_xor_sync(0xFF, w, s);
        if (i == 0) g_bias[o] = w;
    }
}

// ---------------------------------------------------------------------------
// Persistent fused GEMM: 148 CTAs, W slice resident in SMEM
// ---------------------------------------------------------------------------
__global__ __launch_bounds__(NTHREADS, 1)
void kan_gemm_kernel(const float* __restrict__ X, float* __restrict__ Y) {
    extern __shared__ char smem[];
    const uint32_t sbase = smem_u32(smem);
    const int tid  = threadIdx.x;
    const int warp = tid >> 5;          // 0..7
    const int lane = tid & 31;
    const int pos   = warp >> 1;        // 0..3 : warp-tile position
    const int khalf = warp & 1;         // 0/1  : k-split half
    const int wr = pos >> 1;            // 0..1 : 64-row band
    const int wc = pos & 1;             // 0..1 : 32-col band
    const int g  = lane >> 2;
    const int tig = lane & 3;

    const int col   = blockIdx.x & 3;         // col slice 0..3
    const int rid   = blockIdx.x >> 2;        // 0..36
    const int colbase = col * BN;

    // ---- W prologue: load 64-col slice once (64 x 2048B, stride 2064) ----
    #pragma unroll
    for (int c = 0; c < 32; ++c) {
        int chunk = tid + c * NTHREADS;       // 0..8191
        int col_l = chunk >> 7;               // 0..63
        int seg   = chunk & 127;              // 0..127 (16B units)
        cp_async16(sbase + SM_W + (uint32_t)col_l * WSTRIDE + seg * 16,
                   g_W + (size_t)(colbase + col_l) * KDIM + seg * 8);
    }
    cp_commit();

    // ldmatrix per-thread base offsets
    const uint32_t a_lds = (uint32_t)(wr * 64 + (lane & 7) + ((lane >> 3) & 1) * 8)
                           * (SA * 2) + ((lane >> 4) & 1) * 16;
    const uint32_t b_base = sbase + SM_W
        + (uint32_t)(wc * 32 + (lane & 7) + ((lane >> 4) & 1) * 8) * WSTRIDE
        + ((lane >> 3) & 1) * 16;
    const int kb0 = khalf * 2;                // this warp's first kk of each kt

    float acc[4][4][4];
    #pragma unroll
    for (int mt = 0; mt < 4; ++mt)
        #pragma unroll
        for (int nt = 0; nt < 4; ++nt)
            #pragma unroll
            for (int q = 0; q < 4; ++q) acc[mt][nt][q] = 0.0f;

    cp_wait0();
    __syncthreads();      // W slice resident for the rest of the kernel

    for (int tile = rid; tile < NTILES; tile += NRCTA) {
        const int rowbase = tile * BM;

        // ---- stage A(kt=0) into buf0 ----
        #pragma unroll
        for (int j = 0; j < 2; ++j) {
            int e = tid + j * NTHREADS;        // 0..511
            int r = e >> 2;                    // 0..127
            int grp = e & 3;
            float4 xv = *(const float4*)(X + (size_t)(rowbase + r) * IN_DIM + grp * 4);
            float t0 = tanh_fast(xv.x), t1 = tanh_fast(xv.y);
            float t2 = tanh_fast(xv.z), t3 = tanh_fast(xv.w);
            float s0 = t0*t0, s1 = t1*t1, s2 = t2*t2, s3 = t3*t3;
            uint4 c01, c23;
            c01.x = pack_h2(t0, s0); c01.y = pack_h2(s0*t0, s0*s0);
            c01.z = pack_h2(t1, s1); c01.w = pack_h2(s1*t1, s1*s1);
            c23.x = pack_h2(t2, s2); c23.y = pack_h2(s2*t2, s2*s2);
            c23.z = pack_h2(t3, s3); c23.w = pack_h2(s3*t3, s3*s3);
            uint32_t off = (uint32_t)r * (SA * 2) + (uint32_t)grp * 32;
            *(uint4*)(smem + SM_A0 + off)      = c01;
            *(uint4*)(smem + SM_A0 + off + 16) = c23;
        }

        for (int kt = 0; kt < NKT; ++kt) {
            const uint32_t Ab  = sbase + ((kt & 1) ? SM_A1 : SM_A0);
            const uint32_t Abn = sbase + ((kt & 1) ? SM_A0 : SM_A1);

            float4 xv0, xv1;
            if (kt + 1 < NKT) {
                int e0 = tid, e1 = tid + NTHREADS;
                xv0 = *(const float4*)(X + (size_t)(rowbase + (e0 >> 2)) * IN_DIM
                                       + (kt + 1) * 16 + (e0 & 3) * 4);
                xv1 = *(const float4*)(X + (size_t)(rowbase + (e1 >> 2)) * IN_DIM
                                       + (kt + 1) * 16 + (e1 & 3) * 4);
            }

            __syncthreads();   // A(kt) visible; all warps done reading other buf

            // ---- this warp's 2 kk-steps: load both frag sets, then MMA ----
            uint32_t fa[2][4][4], fb[2][2][4];
            const uint32_t wkt = (uint32_t)kt * 128;
            #pragma unroll
            for (int s = 0; s < 2; ++s) {
                const uint32_t ko = (uint32_t)(kb0 + s) * 32;
                #pragma unroll
                for (int mt = 0; mt < 4; ++mt)
                    ldsm_x4(fa[s][mt][0], fa[s][mt][1], fa[s][mt][2], fa[s][mt][3],
                            Ab + a_lds + mt * 16 * (SA * 2) + ko);
                #pragma unroll
                for (int ntp = 0; ntp < 2; ++ntp)
                    ldsm_x4(fb[s][ntp][0], fb[s][ntp][1], fb[s][ntp][2], fb[s][ntp][3],
                            b_base + ntp * 16 * WSTRIDE + wkt + ko);
            }
            #pragma unroll
            for (int s = 0; s < 2; ++s) {
                #pragma unroll
                for (int ntp = 0; ntp < 2; ++ntp) {
                    #pragma unroll
                    for (int h = 0; h < 2; ++h) {
                        const int nt = ntp * 2 + h;
                        #pragma unroll
                        for (int mt = 0; mt < 4; ++mt) {
                            asm volatile(
                                "mma.sync.aligned.m16n8k16.row.col.f32.f16.f16.f32 "
                                "{%0,%1,%2,%3}, {%4,%5,%6,%7}, {%8,%9}, {%0,%1,%2,%3};\n"
                                : "+f"(acc[mt][nt][0]), "+f"(acc[mt][nt][1]),
                                  "+f"(acc[mt][nt][2]), "+f"(acc[mt][nt][3])
                                : "r"(fa[s][mt][0]), "r"(fa[s][mt][1]),
                                  "r"(fa[s][mt][2]), "r"(fa[s][mt][3]),
                                  "r"(fb[s][ntp][h * 2]), "r"(fb[s][ntp][h * 2 + 1]));
                        }
                    }
                }
            }

            // ---- stage A(kt+1) into other buffer ----
            if (kt + 1 < NKT) {
                #pragma unroll
                for (int j = 0; j < 2; ++j) {
                    float4 xv = j ? xv1 : xv0;
                    int e = tid + j * NTHREADS;
                    int r = e >> 2;
                    int grp = e & 3;
                    float t0 = tanh_fast(xv.x), t1 = tanh_fast(xv.y);
                    float t2 = tanh_fast(xv.z), t3 = tanh_fast(xv.w);
                    float s0 = t0*t0, s1 = t1*t1, s2 = t2*t2, s3 = t3*t3;
                    uint4 c01, c23;
                    c01.x = pack_h2(t0, s0); c01.y = pack_h2(s0*t0, s0*s0);
                    c01.z = pack_h2(t1, s1); c01.w = pack_h2(s1*t1, s1*s1);
                    c23.x = pack_h2(t2, s2); c23.y = pack_h2(s2*t2, s2*s2);
                    c23.z = pack_h2(t3, s3); c23.w = pack_h2(s3*t3, s3*s3);
                    uint32_t off = (uint32_t)r * (SA * 2) + (uint32_t)grp * 32;
                    *(uint4*)((char*)smem + (Abn - sbase) + off)      = c01;
                    *(uint4*)((char*)smem + (Abn - sbase) + off + 16) = c23;
                }
            }
        }

        // ---- epilogue: reduce k-split partials, + bias, store ----
        __syncthreads();   // all MMAs done; scratch free
        if (khalf == 1) {
            #pragma unroll
            for (int mt = 0; mt < 4; ++mt)
                #pragma unroll
                for (int nt = 0; nt < 4; ++nt) {
                    int q4 = mt * 4 + nt;
                    *(float4*)(smem + SM_RED + pos * 8192 + q4 * 512 + lane * 16)
                        = *(float4*)acc[mt][nt];
                }
        }
        __syncthreads();
        if (khalf == 0) {
            #pragma unroll
            for (int mt = 0; mt < 4; ++mt) {
                int r0 = rowbase + wr * 64 + mt * 16;
                #pragma unroll
                for (int nt = 0; nt < 4; ++nt) {
                    int q4 = mt * 4 + nt;
                    float4 other = *(const float4*)(smem + SM_RED + pos * 8192
                                                    + q4 * 512 + lane * 16);
                    int c0 = colbase + wc * 32 + nt * 8 + tig * 2;
                    float b0 = __ldg(&g_bias[c0]);
                    float b1 = __ldg(&g_bias[c0 + 1]);
                    int r = r0 + g;
                    float2 lo = make_float2(acc[mt][nt][0] + other.x + b0,
                                            acc[mt][nt][1] + other.y + b1);
                    float2 hi = make_float2(acc[mt][nt][2] + other.z + b0,
                                            acc[mt][nt][3] + other.w + b1);
                    *(float2*)(Y + (size_t)r * OUT_DIM + c0)       = lo;
                    *(float2*)(Y + (size_t)(r + 8) * OUT_DIM + c0) = hi;
                }
            }
        }
        // reset accumulators for next tile
        #pragma unroll
        for (int mt = 0; mt < 4; ++mt)
            #pragma unroll
            for (int nt = 0; nt < 4; ++nt)
                #pragma unroll
                for (int q = 0; q < 4; ++q) acc[mt][nt][q] = 0.0f;
    }
}

// ---------------------------------------------------------------------------
extern "C" void kernel_launch(void* const* d_in, const int* in_sizes, int n_in,
                              void* d_out, int out_size) {
    const float* x = (const float*)d_in[0];
    const float* coeffs = (const float*)d_in[1];
    if (n_in >= 2 && in_sizes[0] == OUT_DIM * IN_DIM * 6) {
        coeffs = (const float*)d_in[0];
        x = (const float*)d_in[1];
    }
    float* y = (float*)d_out;

    static bool attr_set = false;
    if (!attr_set) {
        cudaFuncSetAttribute(kan_gemm_kernel,
                             cudaFuncAttributeMaxDynamicSharedMemorySize, SM_TOTAL);
        attr_set = true;
    }

    prep_weights_kernel<<<OUT_DIM, IN_DIM>>>(coeffs);
    kan_gemm_kernel<<<NCOLS * NRCTA, NTHREADS, SM_TOTAL>>>(x, y);
}

// round 16
// speedup vs baseline: 1.2720x; 1.2720x over previous
#include <cuda_runtime.h>
#include <cuda_fp16.h>
#include <stdint.h>

// ============================================================================
// FibonacciKAN via monomial re-expansion, legacy mma.sync path (tcgen05 is
// unavailable: harness PTX targets compute_103, 'a'-gated ops rejected).
//   Y[32768,256] = A[32768,1024] @ W[1024,256] + bias, A = powers of tanh(x)
// R15 = R12 (best: 62.1us) + 3-stage W ring (cp.async wait_group 1, prefetch
// distance 2). Removes the L2-latency gate at each iteration head. R13/R14's
// persistent design is abandoned (killed warp-level parallelism: tensor 26%).
// ============================================================================

#define B_ROWS 32768
#define IN_DIM 256
#define OUT_DIM 256
#define KDIM 1024
#define BM 64                 // rows per CTA
#define BN 128                // cols per CTA
#define BK 64
#define NKT (KDIM / BK)       // 16
#define NTHREADS 128

#define SA 72                 // row stride in halves (144 B) -> conflict-free LDSM
#define SWROW 72
#define ABYTES (BM * SA * 2)      // 9216
#define WBYTES (BN * SWROW * 2)   // 18432
#define SM_A0 0
#define SM_A1 (SM_A0 + ABYTES)
#define SM_W0 (SM_A1 + ABYTES)    // 3-buffer ring
#define SM_TOTAL (SM_W0 + 3 * WBYTES)   // 73728 bytes/CTA -> 3 CTAs/SM (221KB)

__device__ __half g_W[OUT_DIM * KDIM];   // [o][k], k-contiguous
__device__ float  g_bias[OUT_DIM];

// ---------------------------------------------------------------------------
__device__ __forceinline__ uint32_t smem_u32(const void* p) {
    uint32_t a;
    asm("{ .reg .u64 t; cvta.to.shared.u64 t, %1; cvt.u32.u64 %0, t; }"
        : "=r"(a) : "l"(p));
    return a;
}
__device__ __forceinline__ void cp_async16(uint32_t dst, const void* src) {
    asm volatile("cp.async.cg.shared.global [%0], [%1], 16;"
                 :: "r"(dst), "l"(src) : "memory");
}
__device__ __forceinline__ void cp_commit() {
    asm volatile("cp.async.commit_group;" ::: "memory");
}
template <int N>
__device__ __forceinline__ void cp_wait() {
    asm volatile("cp.async.wait_group %0;" :: "n"(N) : "memory");
}
__device__ __forceinline__ void ldsm_x4(uint32_t& r0, uint32_t& r1,
                                        uint32_t& r2, uint32_t& r3, uint32_t addr) {
    asm volatile("ldmatrix.sync.aligned.m8n8.x4.shared.b16 {%0,%1,%2,%3}, [%4];"
                 : "=r"(r0), "=r"(r1), "=r"(r2), "=r"(r3) : "r"(addr));
}
__device__ __forceinline__ uint32_t pack_h2(float a, float b) {
    __half2 h = __floats2half2_rn(a, b);
    return *(uint32_t*)&h;
}
__device__ __forceinline__ float tanh_fast(float x) {
    float y;
    asm("tanh.approx.f32 %0, %1;" : "=f"(y) : "f"(x));
    return y;
}

// ---------------------------------------------------------------------------
// Weight prep: C[i][o][d] -> monomial W[o][k=i*4+p] fp16 + bias[o]
// ---------------------------------------------------------------------------
__global__ void prep_weights_kernel(const float* __restrict__ C) {
    int o = blockIdx.x;
    int i = threadIdx.x;
    const float* c = C + ((size_t)i * OUT_DIM + o) * 6;
    float c1 = c[1], c2 = c[2], c3 = c[3], c4 = c[4], c5 = c[5];
    __half2* dst = (__half2*)(g_W + (size_t)o * KDIM + i * 4);
    dst[0] = __floats2half2_rn(c2 + 2.0f * c4, c3 + 3.0f * c5);
    dst[1] = __floats2half2_rn(c4, c5);

    float v = c1 + c3 + c5;
    #pragma unroll
    for (int s = 16; s > 0; s >>= 1)
        v += __shfl_xor_sync(0xFFFFFFFF, v, s);
    __shared__ float sb[8];
    if ((i & 31) == 0) sb[i >> 5] = v;
    __syncthreads();
    if (i < 8) {
        float w = sb[i];
        #pragma unroll
        for (int s = 4; s > 0; s >>= 1)
            w += __shfl_xor_sync(0xFF, w, s);
        if (i == 0) g_bias[o] = w;
    }
}

// ---------------------------------------------------------------------------
// Fused GEMM: 64x128 CTA, 4 warps of 32x64, 3 CTAs/SM, frag double-buffering,
// 3-stage W ring
// ---------------------------------------------------------------------------
__global__ __launch_bounds__(NTHREADS, 3)
void kan_gemm_kernel(const float* __restrict__ X, float* __restrict__ Y) {
    extern __shared__ char smem[];
    const uint32_t sbase = smem_u32(smem);
    const int tid  = threadIdx.x;
    const int warp = tid >> 5;          // 0..3
    const int lane = tid & 31;
    const int wr = warp >> 1;           // 0..1 (32-row warp tiles)
    const int wc = warp & 1;            // 0..1 (64-col warp tiles)
    const int g  = lane >> 2;
    const int tig = lane & 3;
    const int rowbase = (int)(blockIdx.x >> 1) * BM;
    const int colbase = (int)(blockIdx.x & 1) * BN;

    // W staging geometry: 1024 16B chunks, 8 per thread
    const int wrow0 = tid >> 3;         // 0..15 (+16 per j)
    const int wseg  = tid & 7;          // 0..7

    // ldmatrix per-thread base offsets (bytes)
    const uint32_t a_lds = (uint32_t)(wr * 32 + (lane & 7) + ((lane >> 3) & 1) * 8)
                           * (SA * 2) + ((lane >> 4) & 1) * 16;
    const uint32_t b_lds = (uint32_t)(wc * 64 + (lane & 7) + ((lane >> 4) & 1) * 8)
                           * (SWROW * 2) + ((lane >> 3) & 1) * 16;

    float acc[2][8][4];
    #pragma unroll
    for (int mt = 0; mt < 2; ++mt)
        #pragma unroll
        for (int nt = 0; nt < 8; ++nt)
            #pragma unroll
            for (int q = 0; q < 4; ++q) acc[mt][nt][q] = 0.0f;

    // ---- prologue: commit W tiles 0 and 1; stage A tile 0 ----
    #pragma unroll
    for (int j = 0; j < 8; ++j) {
        int nrow = wrow0 + j * 16;
        cp_async16(sbase + SM_W0 + (uint32_t)nrow * (SWROW * 2) + wseg * 16,
                   g_W + (size_t)(colbase + nrow) * KDIM + wseg * 8);
    }
    cp_commit();
    #pragma unroll
    for (int j = 0; j < 8; ++j) {
        int nrow = wrow0 + j * 16;
        cp_async16(sbase + SM_W0 + WBYTES + (uint32_t)nrow * (SWROW * 2) + wseg * 16,
                   g_W + (size_t)(colbase + nrow) * KDIM + BK + wseg * 8);
    }
    cp_commit();
    {
        #pragma unroll
        for (int j = 0; j < 2; ++j) {
            int e = tid + j * NTHREADS;                // 0..255
            int r = e >> 2;                            // 0..63
            int grp = e & 3;
            float4 xv = *(const float4*)(X + (size_t)(rowbase + r) * IN_DIM + grp * 4);
            float t0 = tanh_fast(xv.x), t1 = tanh_fast(xv.y);
            float t2 = tanh_fast(xv.z), t3 = tanh_fast(xv.w);
            float s0 = t0*t0, s1 = t1*t1, s2 = t2*t2, s3 = t3*t3;
            uint4 c01, c23;
            c01.x = pack_h2(t0, s0); c01.y = pack_h2(s0*t0, s0*s0);
            c01.z = pack_h2(t1, s1); c01.w = pack_h2(s1*t1, s1*s1);
            c23.x = pack_h2(t2, s2); c23.y = pack_h2(s2*t2, s2*s2);
            c23.z = pack_h2(t3, s3); c23.w = pack_h2(s3*t3, s3*s3);
            uint32_t off = (uint32_t)r * (SA * 2) + (uint32_t)grp * 32;
            *(uint4*)(smem + SM_A0 + off)      = c01;
            *(uint4*)(smem + SM_A0 + off + 16) = c23;
        }
    }

    for (int kt = 0; kt < NKT; ++kt) {
        const int cur = kt & 1;
        const uint32_t Ab  = sbase + (cur ? SM_A1 : SM_A0);
        const uint32_t Abn = sbase + (cur ? SM_A0 : SM_A1);
        const uint32_t Wb  = sbase + SM_W0 + (kt % 3) * WBYTES;

        // X prefetch for next tile (2 slots per thread)
        float4 xv0, xv1;
        if (kt + 1 < NKT) {
            int e0 = tid, e1 = tid + NTHREADS;
            xv0 = *(const float4*)(X + (size_t)(rowbase + (e0 >> 2)) * IN_DIM
                                   + (kt + 1) * 16 + (e0 & 3) * 4);
            xv1 = *(const float4*)(X + (size_t)(rowbase + (e1 >> 2)) * IN_DIM
                                   + (kt + 1) * 16 + (e1 & 3) * 4);
        }

        cp_wait<1>();          // W tile kt landed (kt+1 may still be in flight)
        __syncthreads();       // A tile kt visible; W buf (kt+2)%3 free

        // commit cp.async for W tile kt+2 (one group per iteration, always)
        if (kt + 2 < NKT) {
            const uint32_t Wbn = sbase + SM_W0 + ((kt + 2) % 3) * WBYTES;
            #pragma unroll
            for (int j = 0; j < 8; ++j) {
                int nrow = wrow0 + j * 16;
                cp_async16(Wbn + (uint32_t)nrow * (SWROW * 2) + wseg * 16,
                           g_W + (size_t)(colbase + nrow) * KDIM + (kt + 2) * BK + wseg * 8);
            }
        }
        cp_commit();

        // ---- MMAs on tile kt: 4 kk-steps, fragments double-buffered ----
        uint32_t fa[2][2][4];   // [set][mt][reg]
        uint32_t fb[2][4][4];   // [set][ntp][reg]

        #pragma unroll
        for (int mt = 0; mt < 2; ++mt)
            ldsm_x4(fa[0][mt][0], fa[0][mt][1], fa[0][mt][2], fa[0][mt][3],
                    Ab + a_lds + mt * 16 * (SA * 2));
        #pragma unroll
        for (int ntp = 0; ntp < 4; ++ntp)
            ldsm_x4(fb[0][ntp][0], fb[0][ntp][1], fb[0][ntp][2], fb[0][ntp][3],
                    Wb + b_lds + ntp * 16 * (SWROW * 2));

        #pragma unroll
        for (int kk = 0; kk < 4; ++kk) {
            const int cs = kk & 1;
            const int ns = cs ^ 1;
            if (kk < 3) {
                #pragma unroll
                for (int mt = 0; mt < 2; ++mt)
                    ldsm_x4(fa[ns][mt][0], fa[ns][mt][1], fa[ns][mt][2], fa[ns][mt][3],
                            Ab + a_lds + mt * 16 * (SA * 2) + (kk + 1) * 32);
                #pragma unroll
                for (int ntp = 0; ntp < 4; ++ntp)
                    ldsm_x4(fb[ns][ntp][0], fb[ns][ntp][1], fb[ns][ntp][2], fb[ns][ntp][3],
                            Wb + b_lds + ntp * 16 * (SWROW * 2) + (kk + 1) * 32);
            }
            #pragma unroll
            for (int ntp = 0; ntp < 4; ++ntp) {
                #pragma unroll
                for (int h = 0; h < 2; ++h) {
                    const int nt = ntp * 2 + h;
                    #pragma unroll
                    for (int mt = 0; mt < 2; ++mt) {
                        asm volatile(
                            "mma.sync.aligned.m16n8k16.row.col.f32.f16.f16.f32 "
                            "{%0,%1,%2,%3}, {%4,%5,%6,%7}, {%8,%9}, {%0,%1,%2,%3};\n"
                            : "+f"(acc[mt][nt][0]), "+f"(acc[mt][nt][1]),
                              "+f"(acc[mt][nt][2]), "+f"(acc[mt][nt][3])
                            : "r"(fa[cs][mt][0]), "r"(fa[cs][mt][1]),
                              "r"(fa[cs][mt][2]), "r"(fa[cs][mt][3]),
                              "r"(fb[cs][ntp][h * 2]), "r"(fb[cs][ntp][h * 2 + 1]));
                    }
                }
            }
        }

        // ---- stage A tile kt+1 ----
        if (kt + 1 < NKT) {
            #pragma unroll
            for (int j = 0; j < 2; ++j) {
                float4 xv = j ? xv1 : xv0;
                int e = tid + j * NTHREADS;
                int r = e >> 2;
                int grp = e & 3;
                float t0 = tanh_fast(xv.x), t1 = tanh_fast(xv.y);
                float t2 = tanh_fast(xv.z), t3 = tanh_fast(xv.w);
                float s0 = t0*t0, s1 = t1*t1, s2 = t2*t2, s3 = t3*t3;
                uint4 c01, c23;
                c01.x = pack_h2(t0, s0); c01.y = pack_h2(s0*t0, s0*s0);
                c01.z = pack_h2(t1, s1); c01.w = pack_h2(s1*t1, s1*s1);
                c23.x = pack_h2(t2, s2); c23.y = pack_h2(s2*t2, s2*s2);
                c23.z = pack_h2(t3, s3); c23.w = pack_h2(s3*t3, s3*s3);
                uint32_t off = (uint32_t)r * (SA * 2) + (uint32_t)grp * 32;
                *(uint4*)((char*)smem + (Abn - sbase) + off)      = c01;
                *(uint4*)((char*)smem + (Abn - sbase) + off + 16) = c23;
            }
        }
    }

    // ---- epilogue: + bias, fp32 store ----
    #pragma unroll
    for (int mt = 0; mt < 2; ++mt) {
        int r0 = rowbase + wr * 32 + mt * 16;
        #pragma unroll
        for (int nt = 0; nt < 8; ++nt) {
            int c0 = colbase + wc * 64 + nt * 8 + tig * 2;
            float b0 = __ldg(&g_bias[c0]);
            float b1 = __ldg(&g_bias[c0 + 1]);
            int r = r0 + g;
            float2 lo = make_float2(acc[mt][nt][0] + b0, acc[mt][nt][1] + b1);
            float2 hi = make_float2(acc[mt][nt][2] + b0, acc[mt][nt][3] + b1);
            *(float2*)(Y + (size_t)r * OUT_DIM + c0)       = lo;
            *(float2*)(Y + (size_t)(r + 8) * OUT_DIM + c0) = hi;
        }
    }
}

// ---------------------------------------------------------------------------
extern "C" void kernel_launch(void* const* d_in, const int* in_sizes, int n_in,
                              void* d_out, int out_size) {
    const float* x = (const float*)d_in[0];
    const float* coeffs = (const float*)d_in[1];
    if (n_in >= 2 && in_sizes[0] == OUT_DIM * IN_DIM * 6) {
        coeffs = (const float*)d_in[0];
        x = (const float*)d_in[1];
    }
    float* y = (float*)d_out;

    static bool attr_set = false;
    if (!attr_set) {
        cudaFuncSetAttribute(kan_gemm_kernel,
                             cudaFuncAttributeMaxDynamicSharedMemorySize, SM_TOTAL);
        attr_set = true;
    }

    prep_weights_kernel<<<OUT_DIM, IN_DIM>>>(coeffs);
    kan_gemm_kernel<<<(B_ROWS / BM) * (OUT_DIM / BN), NTHREADS, SM_TOTAL>>>(x, y);
}